// round 11
// baseline (speedup 1.0000x reference)
#include <cuda_runtime.h>
#include <math.h>

// Problem constants (fixed shapes from setup_inputs)
#define BB   16
#define CC   64
#define HH   256
#define WW   256
#define HWSZ (HH * WW)          // 65536
#define HW4  (HWSZ / 4)         // 16384 float4 per image plane

// Scratch (alloc-free rule: __device__ globals)
__device__ float g_mean [BB * HWSZ];
__device__ float g_max  [BB * HWSZ];
__device__ float g_wx   [BB * HWSZ];
__device__ float g_fused[BB * HWSZ];
__device__ float g_cw   [BB * CC];

__device__ __forceinline__ float sigmoidf_(float v) {
    return 1.0f / (1.0f + expf(-v));
}

// ---------------------------------------------------------------------------
// Pass 1: per-pixel channel mean, channel max, and wr-weighted channel sum.
// Reads x once (268 MB), writes 3 x 4.2 MB planes. Pure HBM streaming.
// One thread = one float4 pixel group; loop over 64 channels (stride HW).
// ---------------------------------------------------------------------------
__global__ __launch_bounds__(256)
void k1_pool(const float* __restrict__ x, const float* __restrict__ wr) {
    __shared__ float swr[CC];
    if (threadIdx.x < CC) swr[threadIdx.x] = wr[threadIdx.x];
    __syncthreads();

    int t = blockIdx.x * 256 + threadIdx.x;      // 0 .. BB*HW4-1
    int b = t >> 14;                             // / HW4
    int p = t & (HW4 - 1);

    const float4* xp = reinterpret_cast<const float4*>(x) + (long)b * CC * HW4 + p;

    float4 v = xp[0];
    float4 s = v;
    float4 m = v;
    float  w0 = swr[0];
    float4 wx = make_float4(w0 * v.x, w0 * v.y, w0 * v.z, w0 * v.w);

#pragma unroll 8
    for (int c = 1; c < CC; c++) {
        v = xp[(long)c * HW4];
        s.x += v.x; s.y += v.y; s.z += v.z; s.w += v.w;
        m.x = fmaxf(m.x, v.x); m.y = fmaxf(m.y, v.y);
        m.z = fmaxf(m.z, v.z); m.w = fmaxf(m.w, v.w);
        float wc = swr[c];
        wx.x = fmaf(wc, v.x, wx.x); wx.y = fmaf(wc, v.y, wx.y);
        wx.z = fmaf(wc, v.z, wx.z); wx.w = fmaf(wc, v.w, wx.w);
    }

    const float inv = 1.0f / (float)CC;
    float4 mean = make_float4(s.x * inv, s.y * inv, s.z * inv, s.w * inv);

    int o = b * HW4 + p;
    reinterpret_cast<float4*>(g_mean)[o] = mean;
    reinterpret_cast<float4*>(g_max )[o] = m;
    reinterpret_cast<float4*>(g_wx  )[o] = wx;
}

// ---------------------------------------------------------------------------
// Pass 2: 3x3 and 5x5 conv (2ch -> 1) on [mean,max], sigmoid, 1x1 fuse, scale.
// Shared-memory halo tile (32x8 outputs, halo 2) -> all conv taps are LDS hits.
// ---------------------------------------------------------------------------
__global__ __launch_bounds__(256)
void k2_conv(const float* __restrict__ w3, const float* __restrict__ b3,
             const float* __restrict__ w5, const float* __restrict__ b5,
             const float* __restrict__ wf, const float* __restrict__ bf) {
    __shared__ float sm[2][12][36];   // [channel][row(8+4)][col(32+4)]
    __shared__ float sw3[18];
    __shared__ float sw5[50];
    __shared__ float sc[5];           // b3, b5, wf0, wf1, bf

    const int b  = blockIdx.z;
    const int x0 = blockIdx.x * 32;
    const int y0 = blockIdx.y * 8;
    const int tx = threadIdx.x;       // 0..31
    const int ty = threadIdx.y;       // 0..7
    const int tid = ty * 32 + tx;

    if (tid < 18)       sw3[tid] = w3[tid];
    else if (tid < 68)  sw5[tid - 18] = w5[tid - 18];
    else if (tid == 68) sc[0] = b3[0];
    else if (tid == 69) sc[1] = b5[0];
    else if (tid == 70) sc[2] = wf[0];
    else if (tid == 71) sc[3] = wf[1];
    else if (tid == 72) sc[4] = bf[0];

    const float* mb = g_mean + b * HWSZ;
    const float* xb = g_max  + b * HWSZ;

    for (int i = tid; i < 12 * 36; i += 256) {
        int r  = i / 36;
        int cc = i - r * 36;
        int gy = y0 + r  - 2;
        int gx = x0 + cc - 2;
        bool ok = (gy >= 0) & (gy < HH) & (gx >= 0) & (gx < WW);
        int gi = gy * WW + gx;
        sm[0][r][cc] = ok ? mb[gi] : 0.0f;
        sm[1][r][cc] = ok ? xb[gi] : 0.0f;
    }
    __syncthreads();

    float c3 = 0.0f, c5 = 0.0f;
#pragma unroll
    for (int kh = 0; kh < 3; kh++)
#pragma unroll
        for (int kw = 0; kw < 3; kw++) {
            c3 = fmaf(sw3[kh * 3 + kw],     sm[0][ty + 1 + kh][tx + 1 + kw], c3);
            c3 = fmaf(sw3[9 + kh * 3 + kw], sm[1][ty + 1 + kh][tx + 1 + kw], c3);
        }
#pragma unroll
    for (int kh = 0; kh < 5; kh++)
#pragma unroll
        for (int kw = 0; kw < 5; kw++) {
            c5 = fmaf(sw5[kh * 5 + kw],      sm[0][ty + kh][tx + kw], c5);
            c5 = fmaf(sw5[25 + kh * 5 + kw], sm[1][ty + kh][tx + kw], c5);
        }

    float a3 = sigmoidf_(c3 + sc[0]);
    float a5 = sigmoidf_(c5 + sc[1]);
    float fused = sc[2] * a3 + sc[3] * a5 + sc[4];
    fused = 0.2f + 0.8f * fused;   // MIN_SCALE + (MAX-MIN)*fused

    g_fused[b * HWSZ + (y0 + ty) * WW + (x0 + tx)] = fused;
}

// ---------------------------------------------------------------------------
// Pass 3+4: per-batch global mean of fused*wx (+br), then tiny 1->32->64 MLP,
// sigmoid -> channel weights cw[b,c]. One block per batch.
// ---------------------------------------------------------------------------
__global__ __launch_bounds__(1024)
void k3_pool_mlp(const float* __restrict__ br,
                 const float* __restrict__ wc1, const float* __restrict__ bc1,
                 const float* __restrict__ wc2, const float* __restrict__ bc2) {
    const int b = blockIdx.x;
    const float4* f4 = reinterpret_cast<const float4*>(g_fused) + b * HW4;
    const float4* w4 = reinterpret_cast<const float4*>(g_wx)    + b * HW4;

    float s = 0.0f;
    for (int i = threadIdx.x; i < HW4; i += 1024) {
        float4 f = f4[i];
        float4 w = w4[i];
        s += f.x * w.x + f.y * w.y + f.z * w.z + f.w * w.w;
    }

    __shared__ float red[1024];
    red[threadIdx.x] = s;
    __syncthreads();
#pragma unroll
    for (int off = 512; off > 0; off >>= 1) {
        if (threadIdx.x < off) red[threadIdx.x] += red[threadIdx.x + off];
        __syncthreads();
    }

    __shared__ float hs[32];
    __shared__ float pooled_s;
    if (threadIdx.x == 0)
        pooled_s = red[0] * (1.0f / (float)HWSZ) + br[0];
    __syncthreads();

    if (threadIdx.x < 32) {
        float hv = wc1[threadIdx.x] * pooled_s + bc1[threadIdx.x];
        hs[threadIdx.x] = hv > 0.0f ? hv : 0.0f;
    }
    __syncthreads();

    if (threadIdx.x < CC) {
        float acc = bc2[threadIdx.x];
#pragma unroll
        for (int j = 0; j < 32; j++)
            acc = fmaf(wc2[threadIdx.x * 32 + j], hs[j], acc);
        g_cw[b * CC + threadIdx.x] = sigmoidf_(acc);
    }
}

// ---------------------------------------------------------------------------
// Pass 5: out = x * (fused * cw[b,c] + 0.7). Second full read of x + write.
// fused plane (4.2 MB total) is L2-resident across the 64-channel reuse.
// ---------------------------------------------------------------------------
__global__ __launch_bounds__(256)
void k5_apply(const float* __restrict__ x, float* __restrict__ out) {
    int i  = blockIdx.x * 256 + threadIdx.x;   // float4 index over [B,C,HW4]
    int hw = i & (HW4 - 1);
    int bc = i >> 14;                          // b*64 + c
    int b  = bc >> 6;

    float cw = __ldg(&g_cw[bc]);
    float4 f = reinterpret_cast<const float4*>(g_fused)[b * HW4 + hw];
    float4 xv = reinterpret_cast<const float4*>(x)[i];

    float4 o;
    o.x = xv.x * fmaf(f.x, cw, 0.7f);
    o.y = xv.y * fmaf(f.y, cw, 0.7f);
    o.z = xv.z * fmaf(f.z, cw, 0.7f);
    o.w = xv.w * fmaf(f.w, cw, 0.7f);
    reinterpret_cast<float4*>(out)[i] = o;
}

// ---------------------------------------------------------------------------
extern "C" void kernel_launch(void* const* d_in, const int* in_sizes, int n_in,
                              void* d_out, int out_size) {
    const float* x   = (const float*)d_in[0];
    const float* w3  = (const float*)d_in[1];
    const float* b3  = (const float*)d_in[2];
    const float* w5  = (const float*)d_in[3];
    const float* b5  = (const float*)d_in[4];
    const float* wf  = (const float*)d_in[5];
    const float* bf  = (const float*)d_in[6];
    const float* wr  = (const float*)d_in[7];
    const float* br  = (const float*)d_in[8];
    const float* wc1 = (const float*)d_in[9];
    const float* bc1 = (const float*)d_in[10];
    const float* wc2 = (const float*)d_in[11];
    const float* bc2 = (const float*)d_in[12];
    float* out = (float*)d_out;

    // Pass 1: channel pool + weighted sum. BB*HW4 = 262144 threads.
    k1_pool<<<(BB * HW4) / 256, 256>>>(x, wr);

    // Pass 2: spatial convs + fuse. tiles: 8 x-tiles, 32 y-tiles, 16 batches.
    dim3 g2(WW / 32, HH / 8, BB);
    dim3 t2(32, 8, 1);
    k2_conv<<<g2, t2>>>(w3, b3, w5, b5, wf, bf);

    // Pass 3+4: per-batch pooled scalar + MLP -> cw.
    k3_pool_mlp<<<BB, 1024>>>(br, wc1, bc1, wc2, bc2);

    // Pass 5: final elementwise. BB*CC*HW4 = 16,777,216 float4 threads.
    k5_apply<<<(BB * CC * HW4) / 256, 256>>>(x, out);
}

// round 12
// speedup vs baseline: 1.0012x; 1.0012x over previous
#include <cuda_runtime.h>
#include <math.h>

// Problem constants (fixed shapes from setup_inputs)
#define BB   16
#define CC   64
#define HH   256
#define WW   256
#define HWSZ (HH * WW)          // 65536
#define HW4  (HWSZ / 4)         // 16384 float4 per image plane

// Scratch (alloc-free rule: __device__ globals)
__device__ float g_mean [BB * HWSZ];
__device__ float g_max  [BB * HWSZ];
__device__ float g_wx   [BB * HWSZ];
__device__ float g_fused[BB * HWSZ];
__device__ float g_cw   [BB * CC];

__device__ __forceinline__ float sigmoidf_(float v) {
    return 1.0f / (1.0f + expf(-v));
}

// ---------------------------------------------------------------------------
// Pass 1: per-pixel channel mean, channel max, and wr-weighted channel sum.
// Reads x once (268 MB), writes 3 x 4.2 MB planes. Pure HBM streaming.
// One thread = one float4 pixel group; loop over 64 channels (stride HW).
// ---------------------------------------------------------------------------
__global__ __launch_bounds__(256)
void k1_pool(const float* __restrict__ x, const float* __restrict__ wr) {
    __shared__ float swr[CC];
    if (threadIdx.x < CC) swr[threadIdx.x] = wr[threadIdx.x];
    __syncthreads();

    int t = blockIdx.x * 256 + threadIdx.x;      // 0 .. BB*HW4-1
    int b = t >> 14;                             // / HW4
    int p = t & (HW4 - 1);

    const float4* xp = reinterpret_cast<const float4*>(x) + (long)b * CC * HW4 + p;

    float4 v = xp[0];
    float4 s = v;
    float4 m = v;
    float  w0 = swr[0];
    float4 wx = make_float4(w0 * v.x, w0 * v.y, w0 * v.z, w0 * v.w);

#pragma unroll 8
    for (int c = 1; c < CC; c++) {
        v = xp[(long)c * HW4];
        s.x += v.x; s.y += v.y; s.z += v.z; s.w += v.w;
        m.x = fmaxf(m.x, v.x); m.y = fmaxf(m.y, v.y);
        m.z = fmaxf(m.z, v.z); m.w = fmaxf(m.w, v.w);
        float wc = swr[c];
        wx.x = fmaf(wc, v.x, wx.x); wx.y = fmaf(wc, v.y, wx.y);
        wx.z = fmaf(wc, v.z, wx.z); wx.w = fmaf(wc, v.w, wx.w);
    }

    const float inv = 1.0f / (float)CC;
    float4 mean = make_float4(s.x * inv, s.y * inv, s.z * inv, s.w * inv);

    int o = b * HW4 + p;
    reinterpret_cast<float4*>(g_mean)[o] = mean;
    reinterpret_cast<float4*>(g_max )[o] = m;
    reinterpret_cast<float4*>(g_wx  )[o] = wx;
}

// ---------------------------------------------------------------------------
// Pass 2: 3x3 and 5x5 conv (2ch -> 1) on [mean,max], sigmoid, 1x1 fuse, scale.
// Shared-memory halo tile (32x8 outputs, halo 2) -> all conv taps are LDS hits.
// ---------------------------------------------------------------------------
__global__ __launch_bounds__(256)
void k2_conv(const float* __restrict__ w3, const float* __restrict__ b3,
             const float* __restrict__ w5, const float* __restrict__ b5,
             const float* __restrict__ wf, const float* __restrict__ bf) {
    __shared__ float sm[2][12][36];   // [channel][row(8+4)][col(32+4)]
    __shared__ float sw3[18];
    __shared__ float sw5[50];
    __shared__ float sc[5];           // b3, b5, wf0, wf1, bf

    const int b  = blockIdx.z;
    const int x0 = blockIdx.x * 32;
    const int y0 = blockIdx.y * 8;
    const int tx = threadIdx.x;       // 0..31
    const int ty = threadIdx.y;       // 0..7
    const int tid = ty * 32 + tx;

    if (tid < 18)       sw3[tid] = w3[tid];
    else if (tid < 68)  sw5[tid - 18] = w5[tid - 18];
    else if (tid == 68) sc[0] = b3[0];
    else if (tid == 69) sc[1] = b5[0];
    else if (tid == 70) sc[2] = wf[0];
    else if (tid == 71) sc[3] = wf[1];
    else if (tid == 72) sc[4] = bf[0];

    const float* mb = g_mean + b * HWSZ;
    const float* xb = g_max  + b * HWSZ;

    for (int i = tid; i < 12 * 36; i += 256) {
        int r  = i / 36;
        int cc = i - r * 36;
        int gy = y0 + r  - 2;
        int gx = x0 + cc - 2;
        bool ok = (gy >= 0) & (gy < HH) & (gx >= 0) & (gx < WW);
        int gi = gy * WW + gx;
        sm[0][r][cc] = ok ? mb[gi] : 0.0f;
        sm[1][r][cc] = ok ? xb[gi] : 0.0f;
    }
    __syncthreads();

    float c3 = 0.0f, c5 = 0.0f;
#pragma unroll
    for (int kh = 0; kh < 3; kh++)
#pragma unroll
        for (int kw = 0; kw < 3; kw++) {
            c3 = fmaf(sw3[kh * 3 + kw],     sm[0][ty + 1 + kh][tx + 1 + kw], c3);
            c3 = fmaf(sw3[9 + kh * 3 + kw], sm[1][ty + 1 + kh][tx + 1 + kw], c3);
        }
#pragma unroll
    for (int kh = 0; kh < 5; kh++)
#pragma unroll
        for (int kw = 0; kw < 5; kw++) {
            c5 = fmaf(sw5[kh * 5 + kw],      sm[0][ty + kh][tx + kw], c5);
            c5 = fmaf(sw5[25 + kh * 5 + kw], sm[1][ty + kh][tx + kw], c5);
        }

    float a3 = sigmoidf_(c3 + sc[0]);
    float a5 = sigmoidf_(c5 + sc[1]);
    float fused = sc[2] * a3 + sc[3] * a5 + sc[4];
    fused = 0.2f + 0.8f * fused;   // MIN_SCALE + (MAX-MIN)*fused

    g_fused[b * HWSZ + (y0 + ty) * WW + (x0 + tx)] = fused;
}

// ---------------------------------------------------------------------------
// Pass 3+4: per-batch global mean of fused*wx (+br), then tiny 1->32->64 MLP,
// sigmoid -> channel weights cw[b,c]. One block per batch.
// ---------------------------------------------------------------------------
__global__ __launch_bounds__(1024)
void k3_pool_mlp(const float* __restrict__ br,
                 const float* __restrict__ wc1, const float* __restrict__ bc1,
                 const float* __restrict__ wc2, const float* __restrict__ bc2) {
    const int b = blockIdx.x;
    const float4* f4 = reinterpret_cast<const float4*>(g_fused) + b * HW4;
    const float4* w4 = reinterpret_cast<const float4*>(g_wx)    + b * HW4;

    float s = 0.0f;
    for (int i = threadIdx.x; i < HW4; i += 1024) {
        float4 f = f4[i];
        float4 w = w4[i];
        s += f.x * w.x + f.y * w.y + f.z * w.z + f.w * w.w;
    }

    __shared__ float red[1024];
    red[threadIdx.x] = s;
    __syncthreads();
#pragma unroll
    for (int off = 512; off > 0; off >>= 1) {
        if (threadIdx.x < off) red[threadIdx.x] += red[threadIdx.x + off];
        __syncthreads();
    }

    __shared__ float hs[32];
    __shared__ float pooled_s;
    if (threadIdx.x == 0)
        pooled_s = red[0] * (1.0f / (float)HWSZ) + br[0];
    __syncthreads();

    if (threadIdx.x < 32) {
        float hv = wc1[threadIdx.x] * pooled_s + bc1[threadIdx.x];
        hs[threadIdx.x] = hv > 0.0f ? hv : 0.0f;
    }
    __syncthreads();

    if (threadIdx.x < CC) {
        float acc = bc2[threadIdx.x];
#pragma unroll
        for (int j = 0; j < 32; j++)
            acc = fmaf(wc2[threadIdx.x * 32 + j], hs[j], acc);
        g_cw[b * CC + threadIdx.x] = sigmoidf_(acc);
    }
}

// ---------------------------------------------------------------------------
// Pass 5: out = x * (fused * cw[b,c] + 0.7). Second full read of x + write.
// fused plane (4.2 MB total) is L2-resident across the 64-channel reuse.
// ---------------------------------------------------------------------------
__global__ __launch_bounds__(256)
void k5_apply(const float* __restrict__ x, float* __restrict__ out) {
    int i  = blockIdx.x * 256 + threadIdx.x;   // float4 index over [B,C,HW4]
    int hw = i & (HW4 - 1);
    int bc = i >> 14;                          // b*64 + c
    int b  = bc >> 6;

    float cw = __ldg(&g_cw[bc]);
    float4 f = reinterpret_cast<const float4*>(g_fused)[b * HW4 + hw];
    float4 xv = reinterpret_cast<const float4*>(x)[i];

    float4 o;
    o.x = xv.x * fmaf(f.x, cw, 0.7f);
    o.y = xv.y * fmaf(f.y, cw, 0.7f);
    o.z = xv.z * fmaf(f.z, cw, 0.7f);
    o.w = xv.w * fmaf(f.w, cw, 0.7f);
    reinterpret_cast<float4*>(out)[i] = o;
}

// ---------------------------------------------------------------------------
extern "C" void kernel_launch(void* const* d_in, const int* in_sizes, int n_in,
                              void* d_out, int out_size) {
    const float* x   = (const float*)d_in[0];
    const float* w3  = (const float*)d_in[1];
    const float* b3  = (const float*)d_in[2];
    const float* w5  = (const float*)d_in[3];
    const float* b5  = (const float*)d_in[4];
    const float* wf  = (const float*)d_in[5];
    const float* bf  = (const float*)d_in[6];
    const float* wr  = (const float*)d_in[7];
    const float* br  = (const float*)d_in[8];
    const float* wc1 = (const float*)d_in[9];
    const float* bc1 = (const float*)d_in[10];
    const float* wc2 = (const float*)d_in[11];
    const float* bc2 = (const float*)d_in[12];
    float* out = (float*)d_out;

    // Pass 1: channel pool + weighted sum. BB*HW4 = 262144 threads.
    k1_pool<<<(BB * HW4) / 256, 256>>>(x, wr);

    // Pass 2: spatial convs + fuse. tiles: 8 x-tiles, 32 y-tiles, 16 batches.
    dim3 g2(WW / 32, HH / 8, BB);
    dim3 t2(32, 8, 1);
    k2_conv<<<g2, t2>>>(w3, b3, w5, b5, wf, bf);

    // Pass 3+4: per-batch pooled scalar + MLP -> cw.
    k3_pool_mlp<<<BB, 1024>>>(br, wc1, bc1, wc2, bc2);

    // Pass 5: final elementwise. BB*CC*HW4 = 16,777,216 float4 threads.
    k5_apply<<<(BB * CC * HW4) / 256, 256>>>(x, out);
}

// round 13
// speedup vs baseline: 1.0616x; 1.0603x over previous
#include <cuda_runtime.h>
#include <math.h>

// Problem constants (fixed shapes from setup_inputs)
#define BB   16
#define CC   64
#define HH   256
#define WW   256
#define HWSZ (HH * WW)          // 65536
#define HW4  (HWSZ / 4)         // 16384 float4 per image plane

// Scratch (alloc-free rule: __device__ globals)
__device__ float g_mean   [BB * HWSZ];
__device__ float g_max    [BB * HWSZ];
__device__ float g_wx     [BB * HWSZ];
__device__ float g_fused  [BB * HWSZ];
__device__ float g_partial[BB * 256];   // per-block fused*wx partial sums (deterministic)
__device__ float g_cw     [BB * CC];

__device__ __forceinline__ float sigmoidf_(float v) {
    return 1.0f / (1.0f + expf(-v));
}

// ---------------------------------------------------------------------------
// Pass 1: per-pixel channel mean, channel max, and wr-weighted channel sum.
// Reads x once (268 MB, default caching so the tail stays L2-resident for k5),
// writes 3 x 4.2 MB planes. Forward block order (tail of x freshest at end).
// ---------------------------------------------------------------------------
__global__ __launch_bounds__(256)
void k1_pool(const float* __restrict__ x, const float* __restrict__ wr) {
    __shared__ float swr[CC];
    if (threadIdx.x < CC) swr[threadIdx.x] = wr[threadIdx.x];
    __syncthreads();

    int t = blockIdx.x * 256 + threadIdx.x;      // 0 .. BB*HW4-1
    int b = t >> 14;                             // / HW4
    int p = t & (HW4 - 1);

    const float4* xp = reinterpret_cast<const float4*>(x) + (long)b * CC * HW4 + p;

    float4 v = xp[0];
    float4 s = v;
    float4 m = v;
    float  w0 = swr[0];
    float4 wx = make_float4(w0 * v.x, w0 * v.y, w0 * v.z, w0 * v.w);

#pragma unroll 8
    for (int c = 1; c < CC; c++) {
        v = xp[(long)c * HW4];
        s.x += v.x; s.y += v.y; s.z += v.z; s.w += v.w;
        m.x = fmaxf(m.x, v.x); m.y = fmaxf(m.y, v.y);
        m.z = fmaxf(m.z, v.z); m.w = fmaxf(m.w, v.w);
        float wc = swr[c];
        wx.x = fmaf(wc, v.x, wx.x); wx.y = fmaf(wc, v.y, wx.y);
        wx.z = fmaf(wc, v.z, wx.z); wx.w = fmaf(wc, v.w, wx.w);
    }

    const float inv = 1.0f / (float)CC;
    float4 mean = make_float4(s.x * inv, s.y * inv, s.z * inv, s.w * inv);

    int o = b * HW4 + p;
    reinterpret_cast<float4*>(g_mean)[o] = mean;
    reinterpret_cast<float4*>(g_max )[o] = m;
    reinterpret_cast<float4*>(g_wx  )[o] = wx;
}

// ---------------------------------------------------------------------------
// Pass 2: 3x3 and 5x5 conv (2ch -> 1) on [mean,max], sigmoid, 1x1 fuse, scale.
// Shared-memory halo tile (32x8 outputs, halo 2) -> all conv taps are LDS hits.
// Also reduces fused*wx per block into g_partial (deterministic, no atomics).
// ---------------------------------------------------------------------------
__global__ __launch_bounds__(256)
void k2_conv(const float* __restrict__ w3, const float* __restrict__ b3,
             const float* __restrict__ w5, const float* __restrict__ b5,
             const float* __restrict__ wf, const float* __restrict__ bf) {
    __shared__ float sm[2][12][36];   // [channel][row(8+4)][col(32+4)]
    __shared__ float sw3[18];
    __shared__ float sw5[50];
    __shared__ float sc[5];           // b3, b5, wf0, wf1, bf
    __shared__ float red[256];

    const int b  = blockIdx.z;
    const int x0 = blockIdx.x * 32;
    const int y0 = blockIdx.y * 8;
    const int tx = threadIdx.x;       // 0..31
    const int ty = threadIdx.y;       // 0..7
    const int tid = ty * 32 + tx;

    if (tid < 18)       sw3[tid] = w3[tid];
    else if (tid < 68)  sw5[tid - 18] = w5[tid - 18];
    else if (tid == 68) sc[0] = b3[0];
    else if (tid == 69) sc[1] = b5[0];
    else if (tid == 70) sc[2] = wf[0];
    else if (tid == 71) sc[3] = wf[1];
    else if (tid == 72) sc[4] = bf[0];

    const float* mb = g_mean + b * HWSZ;
    const float* xb = g_max  + b * HWSZ;

    for (int i = tid; i < 12 * 36; i += 256) {
        int r  = i / 36;
        int cc = i - r * 36;
        int gy = y0 + r  - 2;
        int gx = x0 + cc - 2;
        bool ok = (gy >= 0) & (gy < HH) & (gx >= 0) & (gx < WW);
        int gi = gy * WW + gx;
        sm[0][r][cc] = ok ? mb[gi] : 0.0f;
        sm[1][r][cc] = ok ? xb[gi] : 0.0f;
    }
    __syncthreads();

    float c3 = 0.0f, c5 = 0.0f;
#pragma unroll
    for (int kh = 0; kh < 3; kh++)
#pragma unroll
        for (int kw = 0; kw < 3; kw++) {
            c3 = fmaf(sw3[kh * 3 + kw],     sm[0][ty + 1 + kh][tx + 1 + kw], c3);
            c3 = fmaf(sw3[9 + kh * 3 + kw], sm[1][ty + 1 + kh][tx + 1 + kw], c3);
        }
#pragma unroll
    for (int kh = 0; kh < 5; kh++)
#pragma unroll
        for (int kw = 0; kw < 5; kw++) {
            c5 = fmaf(sw5[kh * 5 + kw],      sm[0][ty + kh][tx + kw], c5);
            c5 = fmaf(sw5[25 + kh * 5 + kw], sm[1][ty + kh][tx + kw], c5);
        }

    float a3 = sigmoidf_(c3 + sc[0]);
    float a5 = sigmoidf_(c5 + sc[1]);
    float fused = sc[2] * a3 + sc[3] * a5 + sc[4];
    fused = 0.2f + 0.8f * fused;   // MIN_SCALE + (MAX-MIN)*fused

    const int gi = (y0 + ty) * WW + (x0 + tx);
    g_fused[b * HWSZ + gi] = fused;

    // Deterministic per-block reduction of fused * wx for the global pool.
    red[tid] = fused * g_wx[b * HWSZ + gi];
    __syncthreads();
#pragma unroll
    for (int off = 128; off > 0; off >>= 1) {
        if (tid < off) red[tid] += red[tid + off];
        __syncthreads();
    }
    if (tid == 0)
        g_partial[b * 256 + blockIdx.y * 8 + blockIdx.x] = red[0];
}

// ---------------------------------------------------------------------------
// Pass 3+4: sum the 256 per-block partials (fixed order), + br, then tiny
// 1->32->64 MLP, sigmoid -> channel weights cw[b,c]. One block per batch.
// ---------------------------------------------------------------------------
__global__ __launch_bounds__(256)
void k3_pool_mlp(const float* __restrict__ br,
                 const float* __restrict__ wc1, const float* __restrict__ bc1,
                 const float* __restrict__ wc2, const float* __restrict__ bc2) {
    const int b = blockIdx.x;
    __shared__ float red[256];
    red[threadIdx.x] = g_partial[b * 256 + threadIdx.x];
    __syncthreads();
#pragma unroll
    for (int off = 128; off > 0; off >>= 1) {
        if (threadIdx.x < off) red[threadIdx.x] += red[threadIdx.x + off];
        __syncthreads();
    }

    __shared__ float hs[32];
    __shared__ float pooled_s;
    if (threadIdx.x == 0)
        pooled_s = red[0] * (1.0f / (float)HWSZ) + br[0];
    __syncthreads();

    if (threadIdx.x < 32) {
        float hv = wc1[threadIdx.x] * pooled_s + bc1[threadIdx.x];
        hs[threadIdx.x] = hv > 0.0f ? hv : 0.0f;
    }
    __syncthreads();

    if (threadIdx.x < CC) {
        float acc = bc2[threadIdx.x];
#pragma unroll
        for (int j = 0; j < 32; j++)
            acc = fmaf(wc2[threadIdx.x * 32 + j], hs[j], acc);
        g_cw[b * CC + threadIdx.x] = sigmoidf_(acc);
    }
}

// ---------------------------------------------------------------------------
// Pass 5: out = x * (fused * cw[b,c] + 0.7). Second full read of x + write.
// REVERSED block order: consumes the tail of x first (freshest in L2 after k1).
// __ldcs / __stcs keep the streams evict-first so they don't flush the
// still-unread portion of x's tail out of L2. 2 float4 per thread for ILP.
// Each block covers 512 consecutive float4 = within one (b,c) plane slice.
// ---------------------------------------------------------------------------
__global__ __launch_bounds__(256)
void k5_apply(const float* __restrict__ x, float* __restrict__ out) {
    const int blk  = (int)gridDim.x - 1 - blockIdx.x;   // reversed traversal
    const int base = blk * 512 + threadIdx.x;           // float4 index
    const int bc   = blk >> 5;                          // 512*32 = 16384 = HW4
    const int b    = bc >> 6;

    const float cw = g_cw[bc];
    const float4* x4 = reinterpret_cast<const float4*>(x);
    const float4* f4 = reinterpret_cast<const float4*>(g_fused) + b * HW4;
    float4*       o4 = reinterpret_cast<float4*>(out);

    const int hw0 = base & (HW4 - 1);
    const int hw1 = (base + 256) & (HW4 - 1);

    float4 xv0 = __ldcs(x4 + base);
    float4 xv1 = __ldcs(x4 + base + 256);
    float4 f0  = f4[hw0];
    float4 f1  = f4[hw1];

    float4 o0, o1;
    o0.x = xv0.x * fmaf(f0.x, cw, 0.7f);
    o0.y = xv0.y * fmaf(f0.y, cw, 0.7f);
    o0.z = xv0.z * fmaf(f0.z, cw, 0.7f);
    o0.w = xv0.w * fmaf(f0.w, cw, 0.7f);
    o1.x = xv1.x * fmaf(f1.x, cw, 0.7f);
    o1.y = xv1.y * fmaf(f1.y, cw, 0.7f);
    o1.z = xv1.z * fmaf(f1.z, cw, 0.7f);
    o1.w = xv1.w * fmaf(f1.w, cw, 0.7f);

    __stcs(o4 + base,       o0);
    __stcs(o4 + base + 256, o1);
}

// ---------------------------------------------------------------------------
extern "C" void kernel_launch(void* const* d_in, const int* in_sizes, int n_in,
                              void* d_out, int out_size) {
    const float* x   = (const float*)d_in[0];
    const float* w3  = (const float*)d_in[1];
    const float* b3  = (const float*)d_in[2];
    const float* w5  = (const float*)d_in[3];
    const float* b5  = (const float*)d_in[4];
    const float* wf  = (const float*)d_in[5];
    const float* bf  = (const float*)d_in[6];
    const float* wr  = (const float*)d_in[7];
    const float* br  = (const float*)d_in[8];
    const float* wc1 = (const float*)d_in[9];
    const float* bc1 = (const float*)d_in[10];
    const float* wc2 = (const float*)d_in[11];
    const float* bc2 = (const float*)d_in[12];
    float* out = (float*)d_out;

    // Pass 1: channel pool + weighted sum. BB*HW4 = 262144 threads.
    k1_pool<<<(BB * HW4) / 256, 256>>>(x, wr);

    // Pass 2: spatial convs + fuse + per-block pool partials.
    dim3 g2(WW / 32, HH / 8, BB);
    dim3 t2(32, 8, 1);
    k2_conv<<<g2, t2>>>(w3, b3, w5, b5, wf, bf);

    // Pass 3+4: per-batch pooled scalar + MLP -> cw. Tiny.
    k3_pool_mlp<<<BB, 256>>>(br, wc1, bc1, wc2, bc2);

    // Pass 5: final elementwise, reversed, 2 float4/thread.
    // BB*CC*HW4 / 512 = 32768 blocks.
    k5_apply<<<(BB * CC * HW4) / 512, 256>>>(x, out);
}